// round 13
// baseline (speedup 1.0000x reference)
#include <cuda_runtime.h>
#include <cstdint>

// ---------------------------------------------------------------------------
// BlockwiseToPixels: out[tok] = x[tok] @ W[idx[tok]] + b[idx[tok]]
// B=32, T=8192 -> N=262144 tokens, D=256, P=64, E=16.
//
// R12 (= R8 resubmit; R12 bench was an infra failure, no kernel signal):
// gather via per-row cp.async.bulk (1KB bulk copies, one op per row)
// completed through mbarrier complete_tx, double-buffered against the
// tf32 mma.sync compute. Removes the LDGSTS issue bottleneck seen in R8 ncu
// (L1 54.6%, 4096 cp.async ops per chunk).
// ---------------------------------------------------------------------------

#define TILE_TOKENS 4096
#define NTHREADS    512
#define D_DIM       256
#define P_DIM       64
#define M_CH        64
#define ROW_BYTES   1024              // one x row = 256 f32
#define XS_STRIDE   260               // 256 + 4 pad (1040B, 16B-multiple)
#define WS_STRIDE   72                // 64 + 8 pad -> B-frag LDS conflict-free

// shared memory layout (float units)
#define WS_OFF      0
#define WS_FLOATS   (D_DIM * WS_STRIDE)          // 18432
#define XS_FLOATS   (M_CH * XS_STRIDE)           // 16640
#define XS0_OFF     (WS_OFF + WS_FLOATS)         // 18432
#define XS1_OFF     (XS0_OFF + XS_FLOATS)        // 35072
#define BIAS_OFF    (XS1_OFF + XS_FLOATS)        // 51712
#define LIST_OFF    (BIAS_OFF + P_DIM)           // 51776
#define CNT_OFF     (LIST_OFF + TILE_TOKENS)     // 55872
#define MBAR_OFF    (CNT_OFF + 4)                // byte 223504, 8B aligned
#define SMEM_FLOATS (MBAR_OFF + 8)
#define SMEM_BYTES  (SMEM_FLOATS * 4)            // 223536 bytes

__device__ __forceinline__ float tf32r(float f) {
    uint32_t u;
    asm("cvt.rna.tf32.f32 %0, %1;" : "=r"(u) : "f"(f));
    return __uint_as_float(u);
}

__device__ __forceinline__ void mma8(float c[4],
                                     uint32_t a0, uint32_t a1, uint32_t a2, uint32_t a3,
                                     uint32_t b0, uint32_t b1) {
    asm volatile(
        "mma.sync.aligned.m16n8k8.row.col.f32.tf32.tf32.f32 "
        "{%0,%1,%2,%3}, {%4,%5,%6,%7}, {%8,%9}, {%0,%1,%2,%3};"
        : "+f"(c[0]), "+f"(c[1]), "+f"(c[2]), "+f"(c[3])
        : "r"(a0), "r"(a1), "r"(a2), "r"(a3), "r"(b0), "r"(b1));
}

__device__ __forceinline__ void mbar_init(uint32_t mbar, uint32_t count) {
    asm volatile("mbarrier.init.shared.b64 [%0], %1;" :: "r"(mbar), "r"(count) : "memory");
}

__device__ __forceinline__ void mbar_expect_tx(uint32_t mbar, uint32_t bytes) {
    asm volatile("mbarrier.arrive.expect_tx.shared.b64 _, [%0], %1;"
                 :: "r"(mbar), "r"(bytes) : "memory");
}

__device__ __forceinline__ void mbar_wait(uint32_t mbar, uint32_t parity) {
    asm volatile(
        "{\n\t"
        ".reg .pred P;\n\t"
        "WL_%=:\n\t"
        "mbarrier.try_wait.parity.acquire.cta.shared::cta.b64 P, [%0], %1, 0x989680;\n\t"
        "@!P bra WL_%=;\n\t"
        "}"
        :: "r"(mbar), "r"(parity) : "memory");
}

__device__ __forceinline__ void bulk_row(uint32_t dst, const void* src, uint32_t mbar) {
    asm volatile(
        "cp.async.bulk.shared::cta.global.mbarrier::complete_tx::bytes [%0], [%1], %2, [%3];"
        :: "r"(dst), "l"(src), "r"((uint32_t)ROW_BYTES), "r"(mbar) : "memory");
}

// Warp 0 issues one 1KB bulk copy per row of the chunk; expect_tx first.
__device__ __forceinline__ void prefetch_chunk(uint32_t xs_base, uint32_t mbar,
                                               const float* __restrict__ x,
                                               const int* __restrict__ list,
                                               int cb, int m, int lane) {
    const int nrows = min(M_CH, m - cb);
    if (lane == 0) mbar_expect_tx(mbar, (uint32_t)nrows * ROW_BYTES);
    __syncwarp();
    if (lane < nrows) {
        int tok = list[cb + lane];
        bulk_row(xs_base + (uint32_t)(lane * XS_STRIDE) * 4u,
                 x + (size_t)tok * D_DIM, mbar);
    }
    int r2 = lane + 32;
    if (r2 < nrows) {
        int tok = list[cb + r2];
        bulk_row(xs_base + (uint32_t)(r2 * XS_STRIDE) * 4u,
                 x + (size_t)tok * D_DIM, mbar);
    }
}

__global__ void __launch_bounds__(NTHREADS, 1)
moe_pixels_kernel(const float* __restrict__ x,
                  const float* __restrict__ W,
                  const float* __restrict__ bias,
                  const int* __restrict__ bidx,
                  float* __restrict__ out,
                  int n_tok) {
    extern __shared__ float sm[];
    float* Ws   = sm + WS_OFF;
    float* Bs   = sm + BIAS_OFF;
    int*   list = (int*)(sm + LIST_OFF);
    int*   cnt  = (int*)(sm + CNT_OFF);

    const int tid       = threadIdx.x;
    const int e         = blockIdx.y;
    const int tile_base = blockIdx.x * TILE_TOKENS;

    const uint32_t smem_u32 = (uint32_t)__cvta_generic_to_shared(sm);
    const uint32_t mbar0 = smem_u32 + MBAR_OFF * 4u;
    const uint32_t mbar1 = mbar0 + 8u;
    const uint32_t xs0   = smem_u32 + XS0_OFF * 4u;
    const uint32_t xs1   = smem_u32 + XS1_OFF * 4u;

    if (tid == 0) {
        *cnt = 0;
        mbar_init(mbar0, 1);
        mbar_init(mbar1, 1);
    }
    __syncthreads();

    // ---- load W[e] into padded smem (tf32-rounded, once) ------------------
    const float4* Wg = (const float4*)(W + (size_t)e * D_DIM * P_DIM);
    for (int i = tid; i < (D_DIM * P_DIM) / 4; i += NTHREADS) {
        int k  = i >> 4;   // 16 float4 per 64-wide row
        int c4 = i & 15;
        float4 v = Wg[i];
        v.x = tf32r(v.x); v.y = tf32r(v.y); v.z = tf32r(v.z); v.w = tf32r(v.w);
        *(float4*)(Ws + k * WS_STRIDE + c4 * 4) = v;
    }
    if (tid < P_DIM) Bs[tid] = bias[e * P_DIM + tid];

    // ---- compact matching token ids ---------------------------------------
    #pragma unroll
    for (int i = 0; i < TILE_TOKENS / NTHREADS; i++) {
        int pos = tile_base + tid + i * NTHREADS;
        if (pos < n_tok && bidx[pos] == e) {
            int p = atomicAdd(cnt, 1);
            list[p] = pos;
        }
    }
    __syncthreads();
    const int m = *cnt;
    const int nch = (m + M_CH - 1) / M_CH;
    if (nch == 0) return;

    const int warp = tid >> 5;
    const int lane = tid & 31;
    const int g    = lane >> 2;   // 0..7
    const int t    = lane & 3;    // 0..3
    const int wr   = warp >> 2;   // 0..3 : row group (16 rows each)
    const int wc   = warp & 3;    // 0..3 : col group (16 cols each)

    // prologue: prefetch chunk 0 into buf0
    if (warp == 0) prefetch_chunk(xs0, mbar0, x, list, 0, m, lane);

    for (int c = 0; c < nch; c++) {
        const int cb = c * M_CH;

        // prefetch chunk c+1 into the other buffer (its prior reader, chunk
        // c-1, finished at the __syncthreads ending iteration c-1)
        if (warp == 0 && c + 1 < nch)
            prefetch_chunk(((c + 1) & 1) ? xs1 : xs0,
                           ((c + 1) & 1) ? mbar1 : mbar0,
                           x, list, cb + M_CH, m, lane);

        // wait for chunk c data (phase flips every 2 chunks per mbar)
        mbar_wait((c & 1) ? mbar1 : mbar0, (c >> 1) & 1);

        const float* Xc = sm + ((c & 1) ? XS1_OFF : XS0_OFF);

        // ---- 64x64x256 tf32 MMA, accumulators seeded with bias ------------
        float acc[2][4];
        #pragma unroll
        for (int nt = 0; nt < 2; nt++) {
            int col = wc * 16 + nt * 8 + 2 * t;
            acc[nt][0] = Bs[col];
            acc[nt][1] = Bs[col + 1];
            acc[nt][2] = acc[nt][0];
            acc[nt][3] = acc[nt][1];
        }

        const float* xa = Xc + (wr * 16 + g) * XS_STRIDE + t;
        #pragma unroll 4
        for (int kk = 0; kk < D_DIM / 8; kk++) {
            const int k0 = kk * 8;
            uint32_t a0 = __float_as_uint(tf32r(xa[k0]));
            uint32_t a1 = __float_as_uint(tf32r(xa[8 * XS_STRIDE + k0]));
            uint32_t a2 = __float_as_uint(tf32r(xa[k0 + 4]));
            uint32_t a3 = __float_as_uint(tf32r(xa[8 * XS_STRIDE + k0 + 4]));
            const float* wb = Ws + (k0 + t) * WS_STRIDE + wc * 16 + g;
            #pragma unroll
            for (int nt = 0; nt < 2; nt++) {
                uint32_t b0 = __float_as_uint(wb[nt * 8]);
                uint32_t b1 = __float_as_uint(wb[4 * WS_STRIDE + nt * 8]);
                mma8(acc[nt], a0, a1, a2, a3, b0, b1);
            }
        }

        // ---- scatter results ----------------------------------------------
        const int rr0  = cb + wr * 16 + g;
        const int rr1  = rr0 + 8;
        const int tok0 = (rr0 < m) ? list[rr0] : -1;
        const int tok1 = (rr1 < m) ? list[rr1] : -1;
        #pragma unroll
        for (int nt = 0; nt < 2; nt++) {
            int col = wc * 16 + nt * 8 + 2 * t;
            if (tok0 >= 0)
                *(float2*)(out + (size_t)tok0 * P_DIM + col) =
                    make_float2(acc[nt][0], acc[nt][1]);
            if (tok1 >= 0)
                *(float2*)(out + (size_t)tok1 * P_DIM + col) =
                    make_float2(acc[nt][2], acc[nt][3]);
        }
        __syncthreads();   // all reads of buf[c&1] done before it is refilled
    }
}

extern "C" void kernel_launch(void* const* d_in, const int* in_sizes, int n_in,
                              void* d_out, int out_size) {
    const float* x    = (const float*)d_in[0];   // [B*T, 256] f32
    const float* W    = (const float*)d_in[1];   // [16, 256, 64] f32
    const float* b    = (const float*)d_in[2];   // [16, 64] f32
    const int*   bidx = (const int*)d_in[3];     // [B*T] i32
    float*       out  = (float*)d_out;           // [B*T, 64] f32

    const int n_tok = in_sizes[3];

    cudaFuncSetAttribute(moe_pixels_kernel,
                         cudaFuncAttributeMaxDynamicSharedMemorySize, SMEM_BYTES);

    dim3 grid((n_tok + TILE_TOKENS - 1) / TILE_TOKENS, 16);
    moe_pixels_kernel<<<grid, NTHREADS, SMEM_BYTES>>>(x, W, b, bidx, out, n_tok);
}

// round 15
// speedup vs baseline: 1.0412x; 1.0412x over previous
#include <cuda_runtime.h>
#include <cstdint>

// ---------------------------------------------------------------------------
// BlockwiseToPixels: out[tok] = x[tok] @ W[idx[tok]] + b[idx[tok]]
// B=32, T=8192 -> N=262144 tokens, D=256, P=64, E=16.
//
// R15 (= R14 resubmit; R14 bench was an infra failure like R12, no signal):
// latency-bound fix. R13 showed no pipe saturated (DRAM 25%, L1 50%,
// tensor 20%, issue 35%) with regs=49 -> ptxas was NOT pipelining the kk
// loop because mma8 was `asm volatile` (a scheduling fence). This round:
//   - non-volatile MMA asm, full kk unroll -> cross-iteration ILP
//   - bias/base-address hoisting out of the chunk loop
// Gather stays: per-row 1KB cp.async.bulk + mbarrier, double-buffered.
// ---------------------------------------------------------------------------

#define TILE_TOKENS 4096
#define NTHREADS    512
#define D_DIM       256
#define P_DIM       64
#define M_CH        64
#define ROW_BYTES   1024              // one x row = 256 f32
#define XS_STRIDE   260               // 256 + 4 pad (1040B, 16B-multiple)
#define WS_STRIDE   72                // 64 + 8 pad -> B-frag LDS conflict-free

// shared memory layout (float units)
#define WS_OFF      0
#define WS_FLOATS   (D_DIM * WS_STRIDE)          // 18432
#define XS_FLOATS   (M_CH * XS_STRIDE)           // 16640
#define XS0_OFF     (WS_OFF + WS_FLOATS)         // 18432
#define XS1_OFF     (XS0_OFF + XS_FLOATS)        // 35072
#define BIAS_OFF    (XS1_OFF + XS_FLOATS)        // 51712
#define LIST_OFF    (BIAS_OFF + P_DIM)           // 51776
#define CNT_OFF     (LIST_OFF + TILE_TOKENS)     // 55872
#define MBAR_OFF    (CNT_OFF + 4)                // byte 223504, 8B aligned
#define SMEM_FLOATS (MBAR_OFF + 8)
#define SMEM_BYTES  (SMEM_FLOATS * 4)            // 223536 bytes

__device__ __forceinline__ float tf32r(float f) {
    uint32_t u;
    asm("cvt.rna.tf32.f32 %0, %1;" : "=r"(u) : "f"(f));
    return __uint_as_float(u);
}

// NOTE: intentionally NOT volatile — register-only asm whose results are
// consumed; lets ptxas software-pipeline LDS/CVT across HMMAs.
__device__ __forceinline__ void mma8(float c[4],
                                     uint32_t a0, uint32_t a1, uint32_t a2, uint32_t a3,
                                     uint32_t b0, uint32_t b1) {
    asm("mma.sync.aligned.m16n8k8.row.col.f32.tf32.tf32.f32 "
        "{%0,%1,%2,%3}, {%4,%5,%6,%7}, {%8,%9}, {%0,%1,%2,%3};"
        : "+f"(c[0]), "+f"(c[1]), "+f"(c[2]), "+f"(c[3])
        : "r"(a0), "r"(a1), "r"(a2), "r"(a3), "r"(b0), "r"(b1));
}

__device__ __forceinline__ void mbar_init(uint32_t mbar, uint32_t count) {
    asm volatile("mbarrier.init.shared.b64 [%0], %1;" :: "r"(mbar), "r"(count) : "memory");
}

__device__ __forceinline__ void mbar_expect_tx(uint32_t mbar, uint32_t bytes) {
    asm volatile("mbarrier.arrive.expect_tx.shared.b64 _, [%0], %1;"
                 :: "r"(mbar), "r"(bytes) : "memory");
}

__device__ __forceinline__ void mbar_wait(uint32_t mbar, uint32_t parity) {
    asm volatile(
        "{\n\t"
        ".reg .pred P;\n\t"
        "WL_%=:\n\t"
        "mbarrier.try_wait.parity.acquire.cta.shared::cta.b64 P, [%0], %1, 0x989680;\n\t"
        "@!P bra WL_%=;\n\t"
        "}"
        :: "r"(mbar), "r"(parity) : "memory");
}

__device__ __forceinline__ void bulk_row(uint32_t dst, const void* src, uint32_t mbar) {
    asm volatile(
        "cp.async.bulk.shared::cta.global.mbarrier::complete_tx::bytes [%0], [%1], %2, [%3];"
        :: "r"(dst), "l"(src), "r"((uint32_t)ROW_BYTES), "r"(mbar) : "memory");
}

// Warp 0 issues one 1KB bulk copy per row of the chunk; expect_tx first.
__device__ __forceinline__ void prefetch_chunk(uint32_t xs_base, uint32_t mbar,
                                               const float* __restrict__ x,
                                               const int* __restrict__ list,
                                               int cb, int m, int lane) {
    const int nrows = min(M_CH, m - cb);
    if (lane == 0) mbar_expect_tx(mbar, (uint32_t)nrows * ROW_BYTES);
    __syncwarp();
    if (lane < nrows) {
        int tok = list[cb + lane];
        bulk_row(xs_base + (uint32_t)(lane * XS_STRIDE) * 4u,
                 x + (size_t)tok * D_DIM, mbar);
    }
    int r2 = lane + 32;
    if (r2 < nrows) {
        int tok = list[cb + r2];
        bulk_row(xs_base + (uint32_t)(r2 * XS_STRIDE) * 4u,
                 x + (size_t)tok * D_DIM, mbar);
    }
}

__global__ void __launch_bounds__(NTHREADS, 1)
moe_pixels_kernel(const float* __restrict__ x,
                  const float* __restrict__ W,
                  const float* __restrict__ bias,
                  const int* __restrict__ bidx,
                  float* __restrict__ out,
                  int n_tok) {
    extern __shared__ float sm[];
    float* Ws   = sm + WS_OFF;
    float* Bs   = sm + BIAS_OFF;
    int*   list = (int*)(sm + LIST_OFF);
    int*   cnt  = (int*)(sm + CNT_OFF);

    const int tid       = threadIdx.x;
    const int e         = blockIdx.y;
    const int tile_base = blockIdx.x * TILE_TOKENS;

    const uint32_t smem_u32 = (uint32_t)__cvta_generic_to_shared(sm);
    const uint32_t mbar0 = smem_u32 + MBAR_OFF * 4u;
    const uint32_t mbar1 = mbar0 + 8u;
    const uint32_t xs0   = smem_u32 + XS0_OFF * 4u;
    const uint32_t xs1   = smem_u32 + XS1_OFF * 4u;

    if (tid == 0) {
        *cnt = 0;
        mbar_init(mbar0, 1);
        mbar_init(mbar1, 1);
    }
    __syncthreads();

    // ---- load W[e] into padded smem (tf32-rounded, once) ------------------
    const float4* Wg = (const float4*)(W + (size_t)e * D_DIM * P_DIM);
    for (int i = tid; i < (D_DIM * P_DIM) / 4; i += NTHREADS) {
        int k  = i >> 4;   // 16 float4 per 64-wide row
        int c4 = i & 15;
        float4 v = Wg[i];
        v.x = tf32r(v.x); v.y = tf32r(v.y); v.z = tf32r(v.z); v.w = tf32r(v.w);
        *(float4*)(Ws + k * WS_STRIDE + c4 * 4) = v;
    }
    if (tid < P_DIM) Bs[tid] = bias[e * P_DIM + tid];

    // ---- compact matching token ids ---------------------------------------
    #pragma unroll
    for (int i = 0; i < TILE_TOKENS / NTHREADS; i++) {
        int pos = tile_base + tid + i * NTHREADS;
        if (pos < n_tok && bidx[pos] == e) {
            int p = atomicAdd(cnt, 1);
            list[p] = pos;
        }
    }
    __syncthreads();
    const int m = *cnt;
    const int nch = (m + M_CH - 1) / M_CH;
    if (nch == 0) return;

    const int warp = tid >> 5;
    const int lane = tid & 31;
    const int g    = lane >> 2;   // 0..7
    const int t    = lane & 3;    // 0..3
    const int wr   = warp >> 2;   // 0..3 : row group (16 rows each)
    const int wc   = warp & 3;    // 0..3 : col group (16 cols each)

    // hoisted loop invariants: bias regs + W base pointer
    float bia[2][2];
    #pragma unroll
    for (int nt = 0; nt < 2; nt++) {
        int col = wc * 16 + nt * 8 + 2 * t;
        bia[nt][0] = Bs[col];
        bia[nt][1] = Bs[col + 1];
    }
    const float* wbase = Ws + t * WS_STRIDE + wc * 16 + g;
    const int    arow  = wr * 16 + g;

    // prologue: prefetch chunk 0 into buf0
    if (warp == 0) prefetch_chunk(xs0, mbar0, x, list, 0, m, lane);

    for (int c = 0; c < nch; c++) {
        const int cb = c * M_CH;

        // prefetch chunk c+1 into the other buffer (its prior reader, chunk
        // c-1, finished at the __syncthreads ending iteration c-1)
        if (warp == 0 && c + 1 < nch)
            prefetch_chunk(((c + 1) & 1) ? xs1 : xs0,
                           ((c + 1) & 1) ? mbar1 : mbar0,
                           x, list, cb + M_CH, m, lane);

        // wait for chunk c data (phase flips every 2 chunks per mbar)
        mbar_wait((c & 1) ? mbar1 : mbar0, (c >> 1) & 1);

        const float* Xc = sm + ((c & 1) ? XS1_OFF : XS0_OFF);

        // ---- 64x64x256 tf32 MMA, accumulators seeded with bias ------------
        float acc[2][4];
        #pragma unroll
        for (int nt = 0; nt < 2; nt++) {
            acc[nt][0] = bia[nt][0];
            acc[nt][1] = bia[nt][1];
            acc[nt][2] = bia[nt][0];
            acc[nt][3] = bia[nt][1];
        }

        const float* xa = Xc + arow * XS_STRIDE + t;
        #pragma unroll
        for (int kk = 0; kk < D_DIM / 8; kk++) {
            const int k0 = kk * 8;
            uint32_t a0 = __float_as_uint(tf32r(xa[k0]));
            uint32_t a1 = __float_as_uint(tf32r(xa[8 * XS_STRIDE + k0]));
            uint32_t a2 = __float_as_uint(tf32r(xa[k0 + 4]));
            uint32_t a3 = __float_as_uint(tf32r(xa[8 * XS_STRIDE + k0 + 4]));
            const float* wb = wbase + k0 * WS_STRIDE;
            #pragma unroll
            for (int nt = 0; nt < 2; nt++) {
                uint32_t b0 = __float_as_uint(wb[nt * 8]);
                uint32_t b1 = __float_as_uint(wb[4 * WS_STRIDE + nt * 8]);
                mma8(acc[nt], a0, a1, a2, a3, b0, b1);
            }
        }

        // ---- scatter results ----------------------------------------------
        const int rr0  = cb + arow;
        const int rr1  = rr0 + 8;
        const int tok0 = (rr0 < m) ? list[rr0] : -1;
        const int tok1 = (rr1 < m) ? list[rr1] : -1;
        #pragma unroll
        for (int nt = 0; nt < 2; nt++) {
            int col = wc * 16 + nt * 8 + 2 * t;
            if (tok0 >= 0)
                *(float2*)(out + (size_t)tok0 * P_DIM + col) =
                    make_float2(acc[nt][0], acc[nt][1]);
            if (tok1 >= 0)
                *(float2*)(out + (size_t)tok1 * P_DIM + col) =
                    make_float2(acc[nt][2], acc[nt][3]);
        }
        __syncthreads();   // all reads of buf[c&1] done before it is refilled
    }
}

extern "C" void kernel_launch(void* const* d_in, const int* in_sizes, int n_in,
                              void* d_out, int out_size) {
    const float* x    = (const float*)d_in[0];   // [B*T, 256] f32
    const float* W    = (const float*)d_in[1];   // [16, 256, 64] f32
    const float* b    = (const float*)d_in[2];   // [16, 64] f32
    const int*   bidx = (const int*)d_in[3];     // [B*T] i32
    float*       out  = (float*)d_out;           // [B*T, 64] f32

    const int n_tok = in_sizes[3];

    cudaFuncSetAttribute(moe_pixels_kernel,
                         cudaFuncAttributeMaxDynamicSharedMemorySize, SMEM_BYTES);

    dim3 grid((n_tok + TILE_TOKENS - 1) / TILE_TOKENS, 16);
    moe_pixels_kernel<<<grid, NTHREADS, SMEM_BYTES>>>(x, W, b, bidx, out, n_tok);
}

// round 16
// speedup vs baseline: 1.0487x; 1.0073x over previous
#include <cuda_runtime.h>
#include <cstdint>

// ---------------------------------------------------------------------------
// BlockwiseToPixels: out[tok] = x[tok] @ W[idx[tok]] + b[idx[tok]]
// B=32, T=8192 -> N=262144 tokens, D=256, P=64, E=16.
//
// R16: explicit software pipelining. R15 proved ptxas will not hoist LDS
// across mma.sync asm (regs 56, issue 33%, nothing saturated). Now the
// SOURCE issues iteration kk+1's fragment loads before iteration kk's MMAs
// (register double-buffering), so LDS latency hides behind MMA by program
// order. W is stored in a (k, k+4)-paired smem layout so each B fragment is
// a single conflict-free LDS.64 (pitch 136 = 8 mod 32).
// Gather unchanged: per-row 1KB cp.async.bulk + mbarrier, double-buffered.
// ---------------------------------------------------------------------------

#define TILE_TOKENS 4096
#define NTHREADS    512
#define D_DIM       256
#define P_DIM       64
#define M_CH        64
#define ROW_BYTES   1024              // one x row = 256 f32
#define XS_STRIDE   260               // 256 + 4 pad -> A-frag LDS conflict-free
#define WP_PITCH    136               // floats per packed-W row; 136%32==8 ->
                                      // float2 B-frag loads conflict-free

// shared memory layout (float units)
#define WS_OFF      0
#define WS_FLOATS   (128 * WP_PITCH)             // 17408 (128 packed rows)
#define XS_FLOATS   (M_CH * XS_STRIDE)           // 16640
#define XS0_OFF     (WS_OFF + WS_FLOATS)         // 17408
#define XS1_OFF     (XS0_OFF + XS_FLOATS)        // 34048
#define BIAS_OFF    (XS1_OFF + XS_FLOATS)        // 50688
#define LIST_OFF    (BIAS_OFF + P_DIM)           // 50752
#define CNT_OFF     (LIST_OFF + TILE_TOKENS)     // 54848
#define MBAR_OFF    (CNT_OFF + 4)                // byte 219408, 8B aligned
#define SMEM_FLOATS (MBAR_OFF + 8)
#define SMEM_BYTES  (SMEM_FLOATS * 4)            // 219440 bytes

__device__ __forceinline__ float tf32r(float f) {
    uint32_t u;
    asm("cvt.rna.tf32.f32 %0, %1;" : "=r"(u) : "f"(f));
    return __uint_as_float(u);
}

__device__ __forceinline__ void mma8(float c[4],
                                     uint32_t a0, uint32_t a1, uint32_t a2, uint32_t a3,
                                     uint32_t b0, uint32_t b1) {
    asm("mma.sync.aligned.m16n8k8.row.col.f32.tf32.tf32.f32 "
        "{%0,%1,%2,%3}, {%4,%5,%6,%7}, {%8,%9}, {%0,%1,%2,%3};"
        : "+f"(c[0]), "+f"(c[1]), "+f"(c[2]), "+f"(c[3])
        : "r"(a0), "r"(a1), "r"(a2), "r"(a3), "r"(b0), "r"(b1));
}

__device__ __forceinline__ void mbar_init(uint32_t mbar, uint32_t count) {
    asm volatile("mbarrier.init.shared.b64 [%0], %1;" :: "r"(mbar), "r"(count) : "memory");
}

__device__ __forceinline__ void mbar_expect_tx(uint32_t mbar, uint32_t bytes) {
    asm volatile("mbarrier.arrive.expect_tx.shared.b64 _, [%0], %1;"
                 :: "r"(mbar), "r"(bytes) : "memory");
}

__device__ __forceinline__ void mbar_wait(uint32_t mbar, uint32_t parity) {
    asm volatile(
        "{\n\t"
        ".reg .pred P;\n\t"
        "WL_%=:\n\t"
        "mbarrier.try_wait.parity.acquire.cta.shared::cta.b64 P, [%0], %1, 0x989680;\n\t"
        "@!P bra WL_%=;\n\t"
        "}"
        :: "r"(mbar), "r"(parity) : "memory");
}

__device__ __forceinline__ void bulk_row(uint32_t dst, const void* src, uint32_t mbar) {
    asm volatile(
        "cp.async.bulk.shared::cta.global.mbarrier::complete_tx::bytes [%0], [%1], %2, [%3];"
        :: "r"(dst), "l"(src), "r"((uint32_t)ROW_BYTES), "r"(mbar) : "memory");
}

// Warp 0 issues one 1KB bulk copy per row of the chunk; expect_tx first.
__device__ __forceinline__ void prefetch_chunk(uint32_t xs_base, uint32_t mbar,
                                               const float* __restrict__ x,
                                               const int* __restrict__ list,
                                               int cb, int m, int lane) {
    const int nrows = min(M_CH, m - cb);
    if (lane == 0) mbar_expect_tx(mbar, (uint32_t)nrows * ROW_BYTES);
    __syncwarp();
    if (lane < nrows) {
        int tok = list[cb + lane];
        bulk_row(xs_base + (uint32_t)(lane * XS_STRIDE) * 4u,
                 x + (size_t)tok * D_DIM, mbar);
    }
    int r2 = lane + 32;
    if (r2 < nrows) {
        int tok = list[cb + r2];
        bulk_row(xs_base + (uint32_t)(r2 * XS_STRIDE) * 4u,
                 x + (size_t)tok * D_DIM, mbar);
    }
}

__global__ void __launch_bounds__(NTHREADS, 1)
moe_pixels_kernel(const float* __restrict__ x,
                  const float* __restrict__ W,
                  const float* __restrict__ bias,
                  const int* __restrict__ bidx,
                  float* __restrict__ out,
                  int n_tok) {
    extern __shared__ float sm[];
    float* Ws   = sm + WS_OFF;
    float* Bs   = sm + BIAS_OFF;
    int*   list = (int*)(sm + LIST_OFF);
    int*   cnt  = (int*)(sm + CNT_OFF);

    const int tid       = threadIdx.x;
    const int e         = blockIdx.y;
    const int tile_base = blockIdx.x * TILE_TOKENS;

    const uint32_t smem_u32 = (uint32_t)__cvta_generic_to_shared(sm);
    const uint32_t mbar0 = smem_u32 + MBAR_OFF * 4u;
    const uint32_t mbar1 = mbar0 + 8u;
    const uint32_t xs0   = smem_u32 + XS0_OFF * 4u;
    const uint32_t xs1   = smem_u32 + XS1_OFF * 4u;

    if (tid == 0) {
        *cnt = 0;
        mbar_init(mbar0, 1);
        mbar_init(mbar1, 1);
    }
    __syncthreads();

    // ---- load W[e] into PAIRED smem layout (tf32-rounded, once) -----------
    // source k (0..255), n (0..63) ->
    //   kk = k>>3, t = k&3, h = (k&7)>>2 : row = kk*4+t, word = 2n+h.
    // B-fragment (k0+t, k0+t+4) for column n becomes one aligned float2.
    const float4* Wg = (const float4*)(W + (size_t)e * D_DIM * P_DIM);
    for (int i = tid; i < (D_DIM * P_DIM) / 4; i += NTHREADS) {
        int k  = i >> 4;   // 16 float4 per 64-wide source row
        int c4 = i & 15;
        float4 v = Wg[i];
        int kk = k >> 3, rem = k & 7, tt = rem & 3, h = rem >> 2;
        float* dst = Ws + (kk * 4 + tt) * WP_PITCH + h;
        int n0 = c4 * 4;
        dst[2 * (n0 + 0)] = tf32r(v.x);
        dst[2 * (n0 + 1)] = tf32r(v.y);
        dst[2 * (n0 + 2)] = tf32r(v.z);
        dst[2 * (n0 + 3)] = tf32r(v.w);
    }
    if (tid < P_DIM) Bs[tid] = bias[e * P_DIM + tid];

    // ---- compact matching token ids ---------------------------------------
    #pragma unroll
    for (int i = 0; i < TILE_TOKENS / NTHREADS; i++) {
        int pos = tile_base + tid + i * NTHREADS;
        if (pos < n_tok && bidx[pos] == e) {
            int p = atomicAdd(cnt, 1);
            list[p] = pos;
        }
    }
    __syncthreads();
    const int m = *cnt;
    const int nch = (m + M_CH - 1) / M_CH;
    if (nch == 0) return;

    const int warp = tid >> 5;
    const int lane = tid & 31;
    const int g    = lane >> 2;   // 0..7
    const int t    = lane & 3;    // 0..3
    const int wr   = warp >> 2;   // 0..3 : row group (16 rows each)
    const int wc   = warp & 3;    // 0..3 : col group (16 cols each)

    // hoisted invariants
    float bia[2][2];
    #pragma unroll
    for (int nt = 0; nt < 2; nt++) {
        int col = wc * 16 + nt * 8 + 2 * t;
        bia[nt][0] = Bs[col];
        bia[nt][1] = Bs[col + 1];
    }
    // B fragment base as float2: word (kk*4+t)*WP_PITCH + 2*col -> f2 index
    // (kk*4+t)*(WP_PITCH/2) + col, with col = wc*16 + nt*8 + g.
    const float2* wb2 = (const float2*)Ws + t * (WP_PITCH / 2) + wc * 16 + g;
    const int arow = wr * 16 + g;

    // prologue: prefetch chunk 0 into buf0
    if (warp == 0) prefetch_chunk(xs0, mbar0, x, list, 0, m, lane);

    for (int c = 0; c < nch; c++) {
        const int cb = c * M_CH;

        if (warp == 0 && c + 1 < nch)
            prefetch_chunk(((c + 1) & 1) ? xs1 : xs0,
                           ((c + 1) & 1) ? mbar1 : mbar0,
                           x, list, cb + M_CH, m, lane);

        mbar_wait((c & 1) ? mbar1 : mbar0, (c >> 1) & 1);

        const float* Xc = sm + ((c & 1) ? XS1_OFF : XS0_OFF);

        float acc[2][4];
        #pragma unroll
        for (int nt = 0; nt < 2; nt++) {
            acc[nt][0] = bia[nt][0];
            acc[nt][1] = bia[nt][1];
            acc[nt][2] = bia[nt][0];
            acc[nt][3] = bia[nt][1];
        }

        const float* xa = Xc + arow * XS_STRIDE + t;

        // ---- manually software-pipelined 64x64x256 tf32 MMA ---------------
        float  ar[2][4];
        float2 bf[2][2];
        // preload kk = 0 fragments
        ar[0][0] = xa[0];
        ar[0][1] = xa[8 * XS_STRIDE];
        ar[0][2] = xa[4];
        ar[0][3] = xa[8 * XS_STRIDE + 4];
        bf[0][0] = wb2[0];
        bf[0][1] = wb2[8];

        #pragma unroll
        for (int kk = 0; kk < D_DIM / 8; kk++) {
            const int cur = kk & 1, nxt = cur ^ 1;
            if (kk < D_DIM / 8 - 1) {
                const int k1 = (kk + 1) * 8;
                ar[nxt][0] = xa[k1];
                ar[nxt][1] = xa[8 * XS_STRIDE + k1];
                ar[nxt][2] = xa[k1 + 4];
                ar[nxt][3] = xa[8 * XS_STRIDE + k1 + 4];
                bf[nxt][0] = wb2[(kk + 1) * 2 * WP_PITCH];      // f2 idx (kk+1)*4*(WP/2)
                bf[nxt][1] = wb2[(kk + 1) * 2 * WP_PITCH + 8];
            }
            uint32_t a0 = __float_as_uint(tf32r(ar[cur][0]));
            uint32_t a1 = __float_as_uint(tf32r(ar[cur][1]));
            uint32_t a2 = __float_as_uint(tf32r(ar[cur][2]));
            uint32_t a3 = __float_as_uint(tf32r(ar[cur][3]));
            mma8(acc[0], a0, a1, a2, a3,
                 __float_as_uint(bf[cur][0].x), __float_as_uint(bf[cur][0].y));
            mma8(acc[1], a0, a1, a2, a3,
                 __float_as_uint(bf[cur][1].x), __float_as_uint(bf[cur][1].y));
        }

        // ---- scatter results ----------------------------------------------
        const int rr0  = cb + arow;
        const int rr1  = rr0 + 8;
        const int tok0 = (rr0 < m) ? list[rr0] : -1;
        const int tok1 = (rr1 < m) ? list[rr1] : -1;
        #pragma unroll
        for (int nt = 0; nt < 2; nt++) {
            int col = wc * 16 + nt * 8 + 2 * t;
            if (tok0 >= 0)
                *(float2*)(out + (size_t)tok0 * P_DIM + col) =
                    make_float2(acc[nt][0], acc[nt][1]);
            if (tok1 >= 0)
                *(float2*)(out + (size_t)tok1 * P_DIM + col) =
                    make_float2(acc[nt][2], acc[nt][3]);
        }
        __syncthreads();   // all reads of buf[c&1] done before it is refilled
    }
}

extern "C" void kernel_launch(void* const* d_in, const int* in_sizes, int n_in,
                              void* d_out, int out_size) {
    const float* x    = (const float*)d_in[0];   // [B*T, 256] f32
    const float* W    = (const float*)d_in[1];   // [16, 256, 64] f32
    const float* b    = (const float*)d_in[2];   // [16, 64] f32
    const int*   bidx = (const int*)d_in[3];     // [B*T] i32
    float*       out  = (float*)d_out;           // [B*T, 64] f32

    const int n_tok = in_sizes[3];

    cudaFuncSetAttribute(moe_pixels_kernel,
                         cudaFuncAttributeMaxDynamicSharedMemorySize, SMEM_BYTES);

    dim3 grid((n_tok + TILE_TOKENS - 1) / TILE_TOKENS, 16);
    moe_pixels_kernel<<<grid, NTHREADS, SMEM_BYTES>>>(x, W, b, bidx, out, n_tok);
}